// round 1
// baseline (speedup 1.0000x reference)
#include <cuda_runtime.h>
#include <cuda_bf16.h>
#include <math.h>

// Problem constants (fixed by reference setup_inputs)
#define NN 100000      // nodes
#define NE 1600000     // edges
#define NG 256         // graphs
#define NH 256         // hidden
#define NF 7           // extra graph features
#define H1 128         // MLP hidden
#define BN_EPS 1e-5f

// ---------------- scratch (device globals; no allocation allowed) ------------
__device__ float g_deg[NN];     // degree (init 1.0 = self loop)
__device__ float g_dinv[NN];    // rsqrt(deg)
__device__ float g_p[NN];       // dinv * x
__device__ float g_t[NN];       // sum over incoming edges of p[src]
__device__ float g_S[NG * NH];  // per-graph per-channel sums of u
__device__ float g_sum[NH];     // sum of u over all nodes
__device__ float g_sumsq[NH];   // sum of u^2
__device__ float g_scale[NH];   // BN scale  = gamma * rsqrt(var+eps)
__device__ float g_shift[NH];   // BN shift  = beta - mean*scale
__device__ float g_cnt[NG];     // nodes per graph

__device__ __forceinline__ float gelu_f(float z) {
    return 0.5f * z * (1.0f + erff(z * 0.70710678118654752f));
}

// ---------------- kernels ----------------------------------------------------

__global__ void init_kernel() {
    int i = blockIdx.x * blockDim.x + threadIdx.x;
    if (i < NN) { g_deg[i] = 1.0f; g_t[i] = 0.0f; }
    if (i < NG * NH) g_S[i] = 0.0f;
    if (i < NH) { g_sum[i] = 0.0f; g_sumsq[i] = 0.0f; }
}

// deg[dst] += 1 over all edges (int4-vectorized; NE % 4 == 0)
__global__ void deg_kernel(const int* __restrict__ dst) {
    int i = (blockIdx.x * blockDim.x + threadIdx.x) * 4;
    if (i + 3 < NE) {
        int4 d = *reinterpret_cast<const int4*>(dst + i);
        atomicAdd(&g_deg[d.x], 1.0f);
        atomicAdd(&g_deg[d.y], 1.0f);
        atomicAdd(&g_deg[d.z], 1.0f);
        atomicAdd(&g_deg[d.w], 1.0f);
    }
}

__global__ void node_prep_kernel(const float* __restrict__ x) {
    int i = blockIdx.x * blockDim.x + threadIdx.x;
    if (i < NN) {
        float dv = rsqrtf(g_deg[i]);   // deg >= 1 always (self loop)
        g_dinv[i] = dv;
        g_p[i] = dv * x[i];
    }
}

// t[dst] += p[src] over all edges
__global__ void scatter_kernel(const int* __restrict__ src, const int* __restrict__ dst) {
    int i = (blockIdx.x * blockDim.x + threadIdx.x) * 4;
    if (i + 3 < NE) {
        int4 s = *reinterpret_cast<const int4*>(src + i);
        int4 d = *reinterpret_cast<const int4*>(dst + i);
        atomicAdd(&g_t[d.x], g_p[s.x]);
        atomicAdd(&g_t[d.y], g_p[s.y]);
        atomicAdd(&g_t[d.z], g_p[s.z]);
        atomicAdd(&g_t[d.w], g_p[s.w]);
    }
}

// The big O(N*H) kernel: u[n][c] = gelu(s_n * W_c + b_c);
// accumulate per-graph sums (batch is sorted -> run-length flush),
// plus global sum / sumsq per channel for BatchNorm stats.
#define TILE 256
__global__ __launch_bounds__(NH) void node_channel_kernel(
    const int* __restrict__ batch,
    const float* __restrict__ W_conv,
    const float* __restrict__ b_conv)
{
    int c = threadIdx.x;                 // channel, blockDim.x == 256
    int nb = gridDim.x;
    int chunk = (NN + nb - 1) / nb;
    int start = blockIdx.x * chunk;
    int end = min(start + chunk, NN);
    if (start >= end) return;            // uniform across block: safe

    float w  = W_conv[c];
    float bb = b_conv[c];

    __shared__ float sh_s[TILE];
    __shared__ int   sh_b[TILE];

    float sum = 0.0f, sq = 0.0f, acc = 0.0f;
    int cur = batch[start];

    for (int t0 = start; t0 < end; t0 += TILE) {
        int n = t0 + c;
        if (n < end) {
            float dv = g_dinv[n];
            sh_s[c] = dv * (g_t[n] + g_p[n]);   // s_n = dinv*t + dinv^2*x
            sh_b[c] = batch[n];
        }
        __syncthreads();
        int len = min(TILE, end - t0);
        #pragma unroll 4
        for (int k = 0; k < len; k++) {
            int g = sh_b[k];                    // uniform across warp
            if (g != cur) {
                atomicAdd(&g_S[cur * NH + c], acc);
                acc = 0.0f;
                cur = g;
            }
            float v = gelu_f(fmaf(sh_s[k], w, bb));
            acc += v;
            sum += v;
            sq = fmaf(v, v, sq);
        }
        __syncthreads();
    }
    atomicAdd(&g_S[cur * NH + c], acc);
    atomicAdd(&g_sum[c], sum);
    atomicAdd(&g_sumsq[c], sq);
}

// BN stats + per-graph counts (batch sorted -> binary search). 1 block, 256 thr.
__global__ void stats_kernel(const int* __restrict__ batch,
                             const float* __restrict__ gamma,
                             const float* __restrict__ beta)
{
    int c = threadIdx.x;
    const float invN = 1.0f / (float)NN;
    float mean = g_sum[c] * invN;
    float var  = g_sumsq[c] * invN - mean * mean;
    float inv  = rsqrtf(var + BN_EPS);
    float sc   = inv * gamma[c];
    g_scale[c] = sc;
    g_shift[c] = beta[c] - mean * sc;

    // count of nodes with batch[n] == c (c doubles as graph id)
    // lower_bound(c) and lower_bound(c+1)
    int lo = 0, hi = NN;
    while (lo < hi) { int m = (lo + hi) >> 1; if (batch[m] < c) lo = m + 1; else hi = m; }
    int lb = lo;
    lo = lb; hi = NN;
    while (lo < hi) { int m = (lo + hi) >> 1; if (batch[m] < c + 1) lo = m + 1; else hi = m; }
    g_cnt[c] = (float)(lo - lb);
}

// MLP tail: one block per graph, 128 threads (one per hidden unit).
__global__ __launch_bounds__(H1) void mlp_kernel(
    const float* __restrict__ y_feat,
    const float* __restrict__ W1, const float* __restrict__ b1,
    const float* __restrict__ W2, const float* __restrict__ b2,
    float* __restrict__ out)
{
    int g = blockIdx.x;
    int j = threadIdx.x;

    __shared__ float sh_in[NH + NF];
    __shared__ float sh_h[H1];

    float cnt = fmaxf(g_cnt[g], 1.0f);
    float rc = 1.0f / cnt;
    for (int i = j; i < NH; i += H1)
        sh_in[i] = fmaf(g_S[g * NH + i] * rc, g_scale[i], g_shift[i]);
    if (j < NF)
        sh_in[NH + j] = y_feat[g * NF + j];
    __syncthreads();

    float acc = b1[j];
    #pragma unroll 8
    for (int cc = 0; cc < NH + NF; cc++)
        acc = fmaf(sh_in[cc], W1[cc * H1 + j], acc);
    sh_h[j] = gelu_f(acc);
    __syncthreads();

    if (j < 2) {
        float o = b2[j];
        #pragma unroll 8
        for (int k = 0; k < H1; k++)
            o = fmaf(sh_h[k], W2[k * 2 + j], o);
        out[g * 2 + j] = 1.0f / (1.0f + expf(-o));
    }
}

// ---------------- launch ------------------------------------------------------
extern "C" void kernel_launch(void* const* d_in, const int* in_sizes, int n_in,
                              void* d_out, int out_size)
{
    const float* x       = (const float*)d_in[0];
    const int*   eidx    = (const int*)  d_in[1];   // [2, NE]
    const int*   batch   = (const int*)  d_in[2];
    const float* y_feat  = (const float*)d_in[3];
    const float* W_conv  = (const float*)d_in[4];
    const float* b_conv  = (const float*)d_in[5];
    const float* gamma   = (const float*)d_in[6];
    const float* beta    = (const float*)d_in[7];
    const float* W1      = (const float*)d_in[8];
    const float* b1      = (const float*)d_in[9];
    const float* W2      = (const float*)d_in[10];
    const float* b2      = (const float*)d_in[11];
    float* out = (float*)d_out;

    const int* src = eidx;
    const int* dst = eidx + NE;

    init_kernel<<<(NN + 255) / 256, 256>>>();
    deg_kernel<<<(NE / 4 + 255) / 256, 256>>>(dst);
    node_prep_kernel<<<(NN + 255) / 256, 256>>>(x);
    scatter_kernel<<<(NE / 4 + 255) / 256, 256>>>(src, dst);
    node_channel_kernel<<<512, NH>>>(batch, W_conv, b_conv);
    stats_kernel<<<1, 256>>>(batch, gamma, beta);
    mlp_kernel<<<NG, H1>>>(y_feat, W1, b1, W2, b2, out);
}

// round 2
// speedup vs baseline: 1.0014x; 1.0014x over previous
#include <cuda_runtime.h>
#include <cuda_bf16.h>
#include <math.h>

// Problem constants (fixed by reference setup_inputs)
#define NN 100000      // nodes
#define NE 1600000     // edges
#define NG 256         // graphs
#define NH 256         // hidden
#define NF 7           // extra graph features
#define H1 128         // MLP hidden
#define BN_EPS 1e-5f
#define NC_BLOCKS 512

// ---------------- scratch (device globals, zero-initialized at module load;
// the mlp kernel re-zeroes everything it dirtied so every call sees zeros) ----
__device__ int   g_degi[NN];    // edge count per dst (self-loop added later)
__device__ float g_dinv[NN];    // rsqrt(deg+1)
__device__ float g_p[NN];       // dinv * x
__device__ float g_t[NN];       // sum over incoming edges of p[src]
__device__ float g_S[NG * NH];  // per-graph per-channel sums of u
__device__ float g_sum[NH];     // sum of u over all nodes
__device__ float g_sumsq[NH];   // sum of u^2
__device__ float g_scale[NH];   // BN scale = gamma * rsqrt(var+eps)
__device__ float g_shift[NH];   // BN shift = beta - mean*scale
__device__ float g_cnt[NG];     // nodes per graph
__device__ unsigned int g_arrive;  // last-block arrival counter

__device__ __forceinline__ float gelu_f(float z) {
    return 0.5f * z * (1.0f + erff(z * 0.70710678118654752f));
}

// ---------------- kernels ----------------------------------------------------

// degree histogram: 16 edges per thread, int atomics
__global__ void deg_kernel(const int* __restrict__ dst) {
    int base = (blockIdx.x * blockDim.x + threadIdx.x) * 16;
    if (base + 16 <= NE) {
        int4 a = *reinterpret_cast<const int4*>(dst + base);
        int4 b = *reinterpret_cast<const int4*>(dst + base + 4);
        int4 c = *reinterpret_cast<const int4*>(dst + base + 8);
        int4 d = *reinterpret_cast<const int4*>(dst + base + 12);
        atomicAdd(&g_degi[a.x], 1); atomicAdd(&g_degi[a.y], 1);
        atomicAdd(&g_degi[a.z], 1); atomicAdd(&g_degi[a.w], 1);
        atomicAdd(&g_degi[b.x], 1); atomicAdd(&g_degi[b.y], 1);
        atomicAdd(&g_degi[b.z], 1); atomicAdd(&g_degi[b.w], 1);
        atomicAdd(&g_degi[c.x], 1); atomicAdd(&g_degi[c.y], 1);
        atomicAdd(&g_degi[c.z], 1); atomicAdd(&g_degi[c.w], 1);
        atomicAdd(&g_degi[d.x], 1); atomicAdd(&g_degi[d.y], 1);
        atomicAdd(&g_degi[d.z], 1); atomicAdd(&g_degi[d.w], 1);
    }
}

__global__ void node_prep_kernel(const float* __restrict__ x) {
    int i = blockIdx.x * blockDim.x + threadIdx.x;
    if (i < NN) {
        float dv = rsqrtf((float)(g_degi[i] + 1));   // +1 = self loop
        g_dinv[i] = dv;
        g_p[i] = dv * x[i];
    }
}

// t[dst] += p[src]; 8 edges per thread, gathers batched before atomics
__global__ void scatter_kernel(const int* __restrict__ src, const int* __restrict__ dst) {
    int base = (blockIdx.x * blockDim.x + threadIdx.x) * 8;
    if (base + 8 <= NE) {
        int4 s0 = *reinterpret_cast<const int4*>(src + base);
        int4 s1 = *reinterpret_cast<const int4*>(src + base + 4);
        int4 d0 = *reinterpret_cast<const int4*>(dst + base);
        int4 d1 = *reinterpret_cast<const int4*>(dst + base + 4);
        float p0 = g_p[s0.x], p1 = g_p[s0.y], p2 = g_p[s0.z], p3 = g_p[s0.w];
        float p4 = g_p[s1.x], p5 = g_p[s1.y], p6 = g_p[s1.z], p7 = g_p[s1.w];
        atomicAdd(&g_t[d0.x], p0); atomicAdd(&g_t[d0.y], p1);
        atomicAdd(&g_t[d0.z], p2); atomicAdd(&g_t[d0.w], p3);
        atomicAdd(&g_t[d1.x], p4); atomicAdd(&g_t[d1.y], p5);
        atomicAdd(&g_t[d1.z], p6); atomicAdd(&g_t[d1.w], p7);
    }
}

// Big O(N*H) kernel: u[n][c] = gelu(s_n*W_c + b_c); per-graph sums via
// run-length flushing (batch sorted) + per-channel sum/sumsq for BN.
// Last arriving block computes BN scale/shift and per-graph counts.
#define TILE 256
__global__ __launch_bounds__(NH) void node_channel_kernel(
    const int* __restrict__ batch,
    const float* __restrict__ W_conv,
    const float* __restrict__ b_conv,
    const float* __restrict__ gamma,
    const float* __restrict__ beta)
{
    int c = threadIdx.x;                 // channel, blockDim.x == 256
    int chunk = (NN + NC_BLOCKS - 1) / NC_BLOCKS;
    int start = blockIdx.x * chunk;
    int end = min(start + chunk, NN);

    __shared__ float2 sh[TILE];

    if (start < end) {
        float w  = W_conv[c];
        float bb = b_conv[c];

        float sum = 0.0f, sq = 0.0f, acc = 0.0f;
        int cur = batch[start];

        for (int t0 = start; t0 < end; t0 += TILE) {
            int n = t0 + c;
            if (n < end) {
                float dv = g_dinv[n];
                // s_n = dinv*t + dinv^2*x  (g_p = dinv*x)
                sh[c] = make_float2(dv * (g_t[n] + g_p[n]),
                                    __int_as_float(batch[n]));
            }
            __syncthreads();
            int len = min(TILE, end - t0);
            #pragma unroll 8
            for (int k = 0; k < len; k++) {
                float2 v = sh[k];
                int g = __float_as_int(v.y);        // uniform across warp
                if (g != cur) {
                    atomicAdd(&g_S[cur * NH + c], acc);
                    acc = 0.0f;
                    cur = g;
                }
                float u = gelu_f(fmaf(v.x, w, bb));
                acc += u;
                sum += u;
                sq = fmaf(u, u, sq);
            }
            __syncthreads();
        }
        atomicAdd(&g_S[cur * NH + c], acc);
        atomicAdd(&g_sum[c], sum);
        atomicAdd(&g_sumsq[c], sq);
    }

    // ---- last-block epilogue: BN stats + per-graph counts ----
    __threadfence();
    __shared__ unsigned int s_last;
    if (c == 0)
        s_last = (atomicAdd(&g_arrive, 1u) == (unsigned)(gridDim.x - 1));
    __syncthreads();
    if (s_last) {
        const float invN = 1.0f / (float)NN;
        float mean = g_sum[c] * invN;
        float var  = g_sumsq[c] * invN - mean * mean;
        float sc   = rsqrtf(var + BN_EPS) * gamma[c];
        g_scale[c] = sc;
        g_shift[c] = beta[c] - mean * sc;

        // nodes with batch[n] == c (c doubles as graph id): two lower_bounds
        int lo = 0, hi = NN;
        while (lo < hi) { int m = (lo + hi) >> 1; if (batch[m] < c) lo = m + 1; else hi = m; }
        int lb = lo;
        hi = NN;
        while (lo < hi) { int m = (lo + hi) >> 1; if (batch[m] < c + 1) lo = m + 1; else hi = m; }
        g_cnt[c] = (float)(lo - lb);

        if (c == 0) g_arrive = 0;   // reset for next call
    }
}

// MLP tail: one block per graph, 128 threads; also re-zeroes all scratch.
__global__ __launch_bounds__(H1) void mlp_kernel(
    const float* __restrict__ y_feat,
    const float* __restrict__ W1, const float* __restrict__ b1,
    const float* __restrict__ W2, const float* __restrict__ b2,
    float* __restrict__ out)
{
    int g = blockIdx.x;
    int j = threadIdx.x;

    __shared__ float sh_in[NH + NF];
    __shared__ float sh_h[H1];

    float cnt = fmaxf(g_cnt[g], 1.0f);
    float rc = 1.0f / cnt;
    for (int i = j; i < NH; i += H1)
        sh_in[i] = fmaf(g_S[g * NH + i] * rc, g_scale[i], g_shift[i]);
    if (j < NF)
        sh_in[NH + j] = y_feat[g * NF + j];
    __syncthreads();

    // cleanup for next call: zero this graph's g_S row + strided node scratch
    for (int i = j; i < NH; i += H1)
        g_S[g * NH + i] = 0.0f;
    for (int i = g * H1 + j; i < NN; i += NG * H1) {
        g_degi[i] = 0;
        g_t[i] = 0.0f;
    }
    if (g == 0) { g_sum[j] = 0.0f; g_sum[j + H1] = 0.0f;
                  g_sumsq[j] = 0.0f; g_sumsq[j + H1] = 0.0f; }

    float acc = b1[j];
    #pragma unroll 8
    for (int cc = 0; cc < NH + NF; cc++)
        acc = fmaf(sh_in[cc], W1[cc * H1 + j], acc);
    sh_h[j] = gelu_f(acc);
    __syncthreads();

    if (j < 2) {
        float o = b2[j];
        #pragma unroll 8
        for (int k = 0; k < H1; k++)
            o = fmaf(sh_h[k], W2[k * 2 + j], o);
        out[g * 2 + j] = 1.0f / (1.0f + expf(-o));
    }
}

// ---------------- launch ------------------------------------------------------
extern "C" void kernel_launch(void* const* d_in, const int* in_sizes, int n_in,
                              void* d_out, int out_size)
{
    const float* x       = (const float*)d_in[0];
    const int*   eidx    = (const int*)  d_in[1];   // [2, NE]
    const int*   batch   = (const int*)  d_in[2];
    const float* y_feat  = (const float*)d_in[3];
    const float* W_conv  = (const float*)d_in[4];
    const float* b_conv  = (const float*)d_in[5];
    const float* gamma   = (const float*)d_in[6];
    const float* beta    = (const float*)d_in[7];
    const float* W1      = (const float*)d_in[8];
    const float* b1      = (const float*)d_in[9];
    const float* W2      = (const float*)d_in[10];
    const float* b2      = (const float*)d_in[11];
    float* out = (float*)d_out;

    const int* src = eidx;
    const int* dst = eidx + NE;

    deg_kernel<<<(NE / 16 + 255) / 256, 256>>>(dst);
    node_prep_kernel<<<(NN + 255) / 256, 256>>>(x);
    scatter_kernel<<<(NE / 8 + 255) / 256, 256>>>(src, dst);
    node_channel_kernel<<<NC_BLOCKS, NH>>>(batch, W_conv, b_conv, gamma, beta);
    mlp_kernel<<<NG, H1>>>(y_feat, W1, b1, W2, b2, out);
}

// round 3
// speedup vs baseline: 1.0394x; 1.0380x over previous
#include <cuda_runtime.h>
#include <cuda_bf16.h>
#include <math.h>

// Problem constants (fixed by reference setup_inputs)
#define NN 100000      // nodes
#define NE 1600000     // edges
#define NG 256         // graphs
#define NH 256         // hidden
#define NF 7           // extra graph features
#define H1 128         // MLP hidden
#define BN_EPS 1e-5f
#define NC_BLOCKS 1024
#define NC_THREADS 128
#define TILE 128

// ---------------- scratch (device globals, zero-initialized at module load;
// the mlp kernel re-zeroes everything dirtied so every call sees zeros) -------
__device__ int   g_degi[NN];    // edge count per dst (self-loop added later)
__device__ float g_dinv[NN];    // rsqrt(deg+1)
__device__ float g_p[NN];       // dinv * x
__device__ float g_t[NN];       // sum over incoming edges of p[src]
__device__ float g_S[NG * NH];  // per-graph per-channel sums of u
__device__ float g_sum[NH];     // sum of u over all nodes
__device__ float g_sumsq[NH];   // sum of u^2
__device__ float g_scale[NH];   // BN scale = gamma * rsqrt(var+eps)
__device__ float g_shift[NH];   // BN shift = beta - mean*scale
__device__ float g_cnt[NG];     // nodes per graph
__device__ unsigned int g_arrive;  // last-block arrival counter

// exact gelu (MLP tail only — tiny, keep max accuracy)
__device__ __forceinline__ float gelu_f(float z) {
    return 0.5f * z * (1.0f + erff(z * 0.70710678118654752f));
}

// fast gelu from half-argument: input zh = z/2, returns gelu(z).
// erf via Abramowitz-Stegun 7.1.26 (max abs err 1.5e-7):
//   erf(x) = 1 - (((((a5 t + a4)t + a3)t + a2)t + a1)t) e^{-x^2},  t = 1/(1+0.3275911 x)
// gelu(z) = 0.5 z + 0.5|z| erf(|z|/sqrt2) = zh + |zh| * erf(...)
__device__ __forceinline__ float gelu_h(float zh) {
    float az = fabsf(zh);
    float x  = az * 1.41421356237f;          // |z|/sqrt(2)
    float d  = fmaf(0.3275911f, x, 1.0f);
    float t;
    asm("rcp.approx.f32 %0, %1;" : "=f"(t) : "f"(d));
    float e  = __expf(-x * x);
    float p  = fmaf(t, 1.061405429f, -1.453152027f);
    p = fmaf(p, t, 1.421413741f);
    p = fmaf(p, t, -0.284496736f);
    p = fmaf(p, t, 0.254829592f);
    p = p * t;
    float r = fmaf(-p, e, 1.0f);             // erf(|z|/sqrt2)
    return fmaf(az, r, zh);
}

// ---------------- kernels ----------------------------------------------------

// degree histogram: 16 edges per thread, int atomics
__global__ void deg_kernel(const int* __restrict__ dst) {
    int base = (blockIdx.x * blockDim.x + threadIdx.x) * 16;
    if (base + 16 <= NE) {
        int4 a = *reinterpret_cast<const int4*>(dst + base);
        int4 b = *reinterpret_cast<const int4*>(dst + base + 4);
        int4 c = *reinterpret_cast<const int4*>(dst + base + 8);
        int4 d = *reinterpret_cast<const int4*>(dst + base + 12);
        atomicAdd(&g_degi[a.x], 1); atomicAdd(&g_degi[a.y], 1);
        atomicAdd(&g_degi[a.z], 1); atomicAdd(&g_degi[a.w], 1);
        atomicAdd(&g_degi[b.x], 1); atomicAdd(&g_degi[b.y], 1);
        atomicAdd(&g_degi[b.z], 1); atomicAdd(&g_degi[b.w], 1);
        atomicAdd(&g_degi[c.x], 1); atomicAdd(&g_degi[c.y], 1);
        atomicAdd(&g_degi[c.z], 1); atomicAdd(&g_degi[c.w], 1);
        atomicAdd(&g_degi[d.x], 1); atomicAdd(&g_degi[d.y], 1);
        atomicAdd(&g_degi[d.z], 1); atomicAdd(&g_degi[d.w], 1);
    }
}

__global__ void node_prep_kernel(const float* __restrict__ x) {
    int i = blockIdx.x * blockDim.x + threadIdx.x;
    if (i < NN) {
        float dv = rsqrtf((float)(g_degi[i] + 1));   // +1 = self loop
        g_dinv[i] = dv;
        g_p[i] = dv * x[i];
    }
}

// t[dst] += p[src]; 8 edges per thread, gathers batched before atomics
__global__ void scatter_kernel(const int* __restrict__ src, const int* __restrict__ dst) {
    int base = (blockIdx.x * blockDim.x + threadIdx.x) * 8;
    if (base + 8 <= NE) {
        int4 s0 = *reinterpret_cast<const int4*>(src + base);
        int4 s1 = *reinterpret_cast<const int4*>(src + base + 4);
        int4 d0 = *reinterpret_cast<const int4*>(dst + base);
        int4 d1 = *reinterpret_cast<const int4*>(dst + base + 4);
        float p0 = g_p[s0.x], p1 = g_p[s0.y], p2 = g_p[s0.z], p3 = g_p[s0.w];
        float p4 = g_p[s1.x], p5 = g_p[s1.y], p6 = g_p[s1.z], p7 = g_p[s1.w];
        atomicAdd(&g_t[d0.x], p0); atomicAdd(&g_t[d0.y], p1);
        atomicAdd(&g_t[d0.z], p2); atomicAdd(&g_t[d0.w], p3);
        atomicAdd(&g_t[d1.x], p4); atomicAdd(&g_t[d1.y], p5);
        atomicAdd(&g_t[d1.z], p6); atomicAdd(&g_t[d1.w], p7);
    }
}

// Big O(N*H) kernel: u[n][c] = gelu(s_n*W_c + b_c); per-graph sums via
// run-length flushing (batch sorted) + per-channel sum/sumsq for BN.
// 128 threads/block, each thread owns channels c and c+128.
// Last arriving block computes BN scale/shift and per-graph counts.
__global__ __launch_bounds__(NC_THREADS) void node_channel_kernel(
    const int* __restrict__ batch,
    const float* __restrict__ W_conv,
    const float* __restrict__ b_conv,
    const float* __restrict__ gamma,
    const float* __restrict__ beta)
{
    int c0 = threadIdx.x;            // channel pair (c0, c0+128)
    int c1 = c0 + NC_THREADS;
    const int chunk = (NN + NC_BLOCKS - 1) / NC_BLOCKS;   // 98
    int start = blockIdx.x * chunk;
    int end = min(start + chunk, NN);

    __shared__ float2 sh[TILE];

    if (start < end) {
        // fold the 0.5 of gelu into weight/bias: zh = 0.5*(s*w+b)
        float w0 = 0.5f * W_conv[c0], b0 = 0.5f * b_conv[c0];
        float w1 = 0.5f * W_conv[c1], b1 = 0.5f * b_conv[c1];

        // stage tile: s_n = dinv*t + dinv^2*x  (g_p = dinv*x), plus batch id
        int n = start + c0;
        if (n < end) {
            float dv = g_dinv[n];
            sh[c0] = make_float2(dv * (g_t[n] + g_p[n]),
                                 __int_as_float(batch[n]));
        }
        __syncthreads();

        float sum0 = 0.0f, sq0 = 0.0f, acc0 = 0.0f;
        float sum1 = 0.0f, sq1 = 0.0f, acc1 = 0.0f;
        int cur = __float_as_int(sh[0].y);
        int len = end - start;

        #pragma unroll 4
        for (int k = 0; k < len; k++) {
            float2 v = sh[k];
            int g = __float_as_int(v.y);        // uniform across warp
            if (g != cur) {
                atomicAdd(&g_S[cur * NH + c0], acc0);
                atomicAdd(&g_S[cur * NH + c1], acc1);
                acc0 = 0.0f; acc1 = 0.0f;
                cur = g;
            }
            float u0 = gelu_h(fmaf(v.x, w0, b0));
            float u1 = gelu_h(fmaf(v.x, w1, b1));
            acc0 += u0;             acc1 += u1;
            sum0 += u0;             sum1 += u1;
            sq0 = fmaf(u0, u0, sq0); sq1 = fmaf(u1, u1, sq1);
        }
        atomicAdd(&g_S[cur * NH + c0], acc0);
        atomicAdd(&g_S[cur * NH + c1], acc1);
        atomicAdd(&g_sum[c0], sum0);
        atomicAdd(&g_sum[c1], sum1);
        atomicAdd(&g_sumsq[c0], sq0);
        atomicAdd(&g_sumsq[c1], sq1);
    }

    // ---- last-block epilogue: BN stats + per-graph counts ----
    __threadfence();
    __shared__ unsigned int s_last;
    if (c0 == 0)
        s_last = (atomicAdd(&g_arrive, 1u) == (unsigned)(gridDim.x - 1));
    __syncthreads();
    if (s_last) {
        const float invN = 1.0f / (float)NN;
        #pragma unroll
        for (int cc = 0; cc < 2; cc++) {
            int c = c0 + cc * NC_THREADS;
            float mean = g_sum[c] * invN;
            float var  = g_sumsq[c] * invN - mean * mean;
            float sc   = rsqrtf(var + BN_EPS) * gamma[c];
            g_scale[c] = sc;
            g_shift[c] = beta[c] - mean * sc;

            // nodes with batch[n] == c (c doubles as graph id)
            int lo = 0, hi = NN;
            while (lo < hi) { int m = (lo + hi) >> 1; if (batch[m] < c) lo = m + 1; else hi = m; }
            int lb = lo;
            hi = NN;
            while (lo < hi) { int m = (lo + hi) >> 1; if (batch[m] < c + 1) lo = m + 1; else hi = m; }
            g_cnt[c] = (float)(lo - lb);
        }
        if (c0 == 0) g_arrive = 0;   // reset for next call
    }
}

// MLP tail: one block per graph, 128 threads; also re-zeroes all scratch.
__global__ __launch_bounds__(H1) void mlp_kernel(
    const float* __restrict__ y_feat,
    const float* __restrict__ W1, const float* __restrict__ b1,
    const float* __restrict__ W2, const float* __restrict__ b2,
    float* __restrict__ out)
{
    int g = blockIdx.x;
    int j = threadIdx.x;

    __shared__ float sh_in[NH + NF];
    __shared__ float sh_h[H1];

    float cnt = fmaxf(g_cnt[g], 1.0f);
    float rc = 1.0f / cnt;
    for (int i = j; i < NH; i += H1)
        sh_in[i] = fmaf(g_S[g * NH + i] * rc, g_scale[i], g_shift[i]);
    if (j < NF)
        sh_in[NH + j] = y_feat[g * NF + j];
    __syncthreads();

    // cleanup for next call: zero this graph's g_S row + strided node scratch
    for (int i = j; i < NH; i += H1)
        g_S[g * NH + i] = 0.0f;
    for (int i = g * H1 + j; i < NN; i += NG * H1) {
        g_degi[i] = 0;
        g_t[i] = 0.0f;
    }
    if (g == 0) { g_sum[j] = 0.0f; g_sum[j + H1] = 0.0f;
                  g_sumsq[j] = 0.0f; g_sumsq[j + H1] = 0.0f; }

    float acc = b1[j];
    #pragma unroll 8
    for (int cc = 0; cc < NH + NF; cc++)
        acc = fmaf(sh_in[cc], W1[cc * H1 + j], acc);
    sh_h[j] = gelu_f(acc);
    __syncthreads();

    if (j < 2) {
        float o = b2[j];
        #pragma unroll 8
        for (int k = 0; k < H1; k++)
            o = fmaf(sh_h[k], W2[k * 2 + j], o);
        out[g * 2 + j] = 1.0f / (1.0f + expf(-o));
    }
}

// ---------------- launch ------------------------------------------------------
extern "C" void kernel_launch(void* const* d_in, const int* in_sizes, int n_in,
                              void* d_out, int out_size)
{
    const float* x       = (const float*)d_in[0];
    const int*   eidx    = (const int*)  d_in[1];   // [2, NE]
    const int*   batch   = (const int*)  d_in[2];
    const float* y_feat  = (const float*)d_in[3];
    const float* W_conv  = (const float*)d_in[4];
    const float* b_conv  = (const float*)d_in[5];
    const float* gamma   = (const float*)d_in[6];
    const float* beta    = (const float*)d_in[7];
    const float* W1      = (const float*)d_in[8];
    const float* b1      = (const float*)d_in[9];
    const float* W2      = (const float*)d_in[10];
    const float* b2      = (const float*)d_in[11];
    float* out = (float*)d_out;

    const int* src = eidx;
    const int* dst = eidx + NE;

    deg_kernel<<<(NE / 16 + 255) / 256, 256>>>(dst);
    node_prep_kernel<<<(NN + 255) / 256, 256>>>(x);
    scatter_kernel<<<(NE / 8 + 255) / 256, 256>>>(src, dst);
    node_channel_kernel<<<NC_BLOCKS, NC_THREADS>>>(batch, W_conv, b_conv, gamma, beta);
    mlp_kernel<<<NG, H1>>>(y_feat, W1, b1, W2, b2, out);
}